// round 11
// baseline (speedup 1.0000x reference)
#include <cuda_runtime.h>

// Problem constants (fixed by the reference): B=4, S=2048, E=16, H=4, D_K=4
#define BB 4
#define SS 2048
#define EE 16
#define HH 4
#define DK 4
#define NBH (BB*HH)

#define KSPLIT 16
#define KT (SS/KSPLIT)       // 128 keys per split tile
#define THREADS 64
#define QPT 4
#define QBLK (THREADS*QPT)   // 256 queries per CTA

typedef unsigned long long u64;

// Global accumulators. Zero at module load; epi_kernel re-zeroes them after
// reading, so every kernel_launch invocation (correctness run, capture,
// each graph replay) sees them zeroed on entry. attn REDs into them.
// g_acc[b][sq][h][4] (float4 rows), g_l[b][sq][h].
#define ACC_N (BB * SS * HH * 4)
#define L_N   (BB * SS * HH)
__device__ float g_acc[ACC_N];
__device__ float g_l[L_N];

__device__ __forceinline__ float ex2f(float x) {
    float y; asm("ex2.approx.ftz.f32 %0, %1;" : "=f"(y) : "f"(x)); return y;
}
__device__ __forceinline__ u64 pk2(float lo, float hi) {
    u64 r; asm("mov.b64 %0, {%1, %2};" : "=l"(r) : "f"(lo), "f"(hi)); return r;
}
__device__ __forceinline__ void upk2(u64 v, float& lo, float& hi) {
    asm("mov.b64 {%0, %1}, %2;" : "=f"(lo), "=f"(hi) : "l"(v));
}
__device__ __forceinline__ u64 fma2(u64 a, u64 b, u64 c) {
    u64 d; asm("fma.rn.f32x2 %0, %1, %2, %3;" : "=l"(d) : "l"(a), "l"(b), "l"(c)); return d;
}
__device__ __forceinline__ u64 mul2(u64 a, u64 b) {
    u64 d; asm("mul.rn.f32x2 %0, %1, %2;" : "=l"(d) : "l"(a), "l"(b)); return d;
}
__device__ __forceinline__ u64 add2(u64 a, u64 b) {
    u64 d; asm("add.rn.f32x2 %0, %1, %2;" : "=l"(d) : "l"(a), "l"(b)); return d;
}

// ---------------------------------------------------------------------------
// Fused kernel: per-CTA K/V projection of its key tile + attention partials,
// accumulated straight into global memory via RED.ADD (no partial arrays).
// K/V key-pair packed: u64 = (val[key 2j], val[key 2j+1]) per dim.
// Bounded scores (|s_log2| < ~12) -> no max subtraction; split partials
// combine by plain (atomic) addition.
// ---------------------------------------------------------------------------
__global__ void __launch_bounds__(THREADS)
attn_kernel(const float* __restrict__ x,
            const float* __restrict__ theta,
            const float* __restrict__ Wk,
            const float* __restrict__ Wv) {
    __shared__ ulonglong2 Ka[KT/2];      // (d0 pair, d1 pair) per key-pair
    __shared__ ulonglong2 Kb[KT/2];      // (d2 pair, d3 pair)
    __shared__ ulonglong2 Va[KT/2];
    __shared__ ulonglong2 Vb[KT/2];
    __shared__ float wk[DK * EE];
    __shared__ float wv[DK * EE];

    int tid = threadIdx.x;               // 0..63
    int qb  = blockIdx.x;                // 0..7
    int bh  = blockIdx.y;                // 0..15
    int ks  = blockIdx.z;                // 0..15
    int b = bh >> 2, h = bh & 3;

    wk[tid] = Wk[h * DK * EE + tid];
    wv[tid] = Wv[h * DK * EE + tid];

    // ---- queries: q = cos(x+theta) * (0.5*log2 e), duplicated-packed ----
    const float4 thv = *reinterpret_cast<const float4*>(theta + h * DK);
    const float SCL = 0.72134752044448170368f;   // 0.5 * log2(e)
    u64 qd0[QPT], qd1[QPT], qd2[QPT], qd3[QPT];
    int sq0 = qb * QBLK + tid;
    #pragma unroll
    for (int qi = 0; qi < QPT; qi++) {
        int sq = sq0 + qi * THREADS;
        const float4 xq = *reinterpret_cast<const float4*>(
            x + (b * SS + sq) * EE + h * DK);
        float c0 = __cosf(xq.x + thv.x) * SCL;
        float c1 = __cosf(xq.y + thv.y) * SCL;
        float c2 = __cosf(xq.z + thv.z) * SCL;
        float c3 = __cosf(xq.w + thv.w) * SCL;
        qd0[qi] = pk2(c0, c0); qd1[qi] = pk2(c1, c1);
        qd2[qi] = pk2(c2, c2); qd3[qi] = pk2(c3, c3);
    }
    __syncthreads();

    // ---- K/V tile build: thread t computes key tokens (2t, 2t+1) ----
    {
        float kk[2][DK], vv[2][DK];
        #pragma unroll
        for (int t = 0; t < 2; t++) {
            int tok = 2 * tid + t;
            const float4* x4 = reinterpret_cast<const float4*>(
                x + ((b * SS + ks * KT) + tok) * EE);
            float xr[EE];
            #pragma unroll
            for (int r = 0; r < 4; r++) {
                float4 q = x4[r];
                xr[4*r+0] = q.x; xr[4*r+1] = q.y; xr[4*r+2] = q.z; xr[4*r+3] = q.w;
            }
            #pragma unroll
            for (int d = 0; d < DK; d++) {
                float a = 0.f, c = 0.f;
                #pragma unroll
                for (int e = 0; e < EE; e++) {
                    a = fmaf(xr[e], wk[d * EE + e], a);
                    c = fmaf(xr[e], wv[d * EE + e], c);
                }
                kk[t][d] = a; vv[t][d] = c;
            }
        }
        ulonglong2 t0, t1;
        t0.x = pk2(kk[0][0], kk[1][0]); t0.y = pk2(kk[0][1], kk[1][1]);
        t1.x = pk2(kk[0][2], kk[1][2]); t1.y = pk2(kk[0][3], kk[1][3]);
        Ka[tid] = t0; Kb[tid] = t1;
        t0.x = pk2(vv[0][0], vv[1][0]); t0.y = pk2(vv[0][1], vv[1][1]);
        t1.x = pk2(vv[0][2], vv[1][2]); t1.y = pk2(vv[0][3], vv[1][3]);
        Va[tid] = t0; Vb[tid] = t1;
    }
    __syncthreads();

    u64 A0[QPT], A1[QPT], A2[QPT], A3[QPT], L[QPT];
    #pragma unroll
    for (int qi = 0; qi < QPT; qi++) {
        A0[qi] = 0ULL; A1[qi] = 0ULL; A2[qi] = 0ULL; A3[qi] = 0ULL; L[qi] = 0ULL;
    }

    #pragma unroll 4
    for (int jp = 0; jp < KT/2; jp++) {
        ulonglong2 ka = Ka[jp];              // broadcast LDS.128
        ulonglong2 kb = Kb[jp];
        ulonglong2 va = Va[jp];
        ulonglong2 vb = Vb[jp];
        #pragma unroll
        for (int qi = 0; qi < QPT; qi++) {
            u64 s = mul2(qd0[qi], ka.x);
            s = fma2(qd1[qi], ka.y, s);
            s = fma2(qd2[qi], kb.x, s);
            s = fma2(qd3[qi], kb.y, s);       // (score_even, score_odd)
            float se, so; upk2(s, se, so);
            u64 pp = pk2(ex2f(se), ex2f(so));
            L[qi]  = add2(L[qi], pp);
            A0[qi] = fma2(pp, va.x, A0[qi]);
            A1[qi] = fma2(pp, va.y, A1[qi]);
            A2[qi] = fma2(pp, vb.x, A2[qi]);
            A3[qi] = fma2(pp, vb.y, A3[qi]);
        }
    }

    // fire-and-forget RED.ADD into global accumulators
    #pragma unroll
    for (int qi = 0; qi < QPT; qi++) {
        int sq = sq0 + qi * THREADS;
        int row = (b * SS + sq) * HH + h;
        float e0, o0, e1, o1, e2, o2, e3, o3, le, lo;
        upk2(A0[qi], e0, o0); upk2(A1[qi], e1, o1);
        upk2(A2[qi], e2, o2); upk2(A3[qi], e3, o3);
        upk2(L[qi], le, lo);
        float* acc = g_acc + row * 4;
        atomicAdd(acc + 0, e0 + o0);
        atomicAdd(acc + 1, e1 + o1);
        atomicAdd(acc + 2, e2 + o2);
        atomicAdd(acc + 3, e3 + o3);
        atomicAdd(g_l + row, le + lo);
    }
}

// ---------------------------------------------------------------------------
// Epilogue: read accumulators (coalesced), RE-ZERO them for the next launch,
// normalize, out = att @ Wc^T with transposed Wc in smem.
// CTA = 64 tokens, 256 threads, one (token,h) each.
// ---------------------------------------------------------------------------
#define EPI_TOK 64

__global__ void __launch_bounds__(256)
epi_kernel(const float* __restrict__ Wc, float* __restrict__ out) {
    __shared__ float wct[EE * EE];            // wct[e*16+o] = Wc[o*16+e]
    __shared__ float att[EPI_TOK][EE + 1];

    int tid = threadIdx.x;                    // 0..255
    wct[(tid & 15) * EE + (tid >> 4)] = Wc[tid];

    int tl = tid >> 2;                        // local token 0..63
    int h  = tid & 3;
    int row = blockIdx.x * (EPI_TOK * HH) + tid;   // (token,h) linear

    float4 a = reinterpret_cast<const float4*>(g_acc)[row];
    float  l = g_l[row];

    // restore the zero-invariant for the next kernel_launch invocation
    reinterpret_cast<float4*>(g_acc)[row] = make_float4(0.f, 0.f, 0.f, 0.f);
    g_l[row] = 0.f;

    float inv = 1.0f / l;
    float* arow = att[tl] + h * DK;
    arow[0] = a.x * inv; arow[1] = a.y * inv;
    arow[2] = a.z * inv; arow[3] = a.w * inv;
    __syncthreads();

    const float* ar = att[tl];
    float r[4] = {0.f, 0.f, 0.f, 0.f};
    #pragma unroll
    for (int e = 0; e < EE; e++) {
        float av = ar[e];
        #pragma unroll
        for (int d = 0; d < 4; d++)
            r[d] = fmaf(av, wct[e * EE + h * 4 + d], r[d]);
    }
    int tok = blockIdx.x * EPI_TOK + tl;
    reinterpret_cast<float4*>(out + tok * EE)[h] =
        make_float4(r[0], r[1], r[2], r[3]);
}

// ---------------------------------------------------------------------------
extern "C" void kernel_launch(void* const* d_in, const int* in_sizes, int n_in,
                              void* d_out, int out_size) {
    const float* x     = (const float*)d_in[0];
    const float* theta = (const float*)d_in[1];
    const float* Wk    = (const float*)d_in[2];
    const float* Wv    = (const float*)d_in[3];
    const float* Wc    = (const float*)d_in[4];
    float* out = (float*)d_out;

    attn_kernel<<<dim3(SS / QBLK, NBH, KSPLIT), THREADS>>>(x, theta, Wk, Wv);
    epi_kernel<<<(BB * SS) / EPI_TOK, 256>>>(Wc, out);
}

// round 12
// speedup vs baseline: 1.1153x; 1.1153x over previous
#include <cuda_runtime.h>

// Problem constants (fixed by the reference): B=4, S=2048, E=16, H=4, D_K=4
#define BB 4
#define SS 2048
#define EE 16
#define HH 4
#define DK 4
#define NBH (BB*HH)

#define KSPLIT 16
#define KT (SS/KSPLIT)       // 128 keys per split tile
#define THREADS 128
#define QPT 4
#define QBLK (THREADS*QPT)   // 512 queries per CTA

typedef unsigned long long u64;

// Scratch (allocation-free rule: __device__ globals)
// Layout: parta[ks][h][b][sq] as float4 rows; partl[ks][h][b][sq] scalar.
// attn stores lane-consecutive sq (coalesced); epi reads 4-lines/instr.
__device__ float g_parta[KSPLIT * BB * SS * EE];
__device__ float g_partl[KSPLIT * BB * SS * HH];

__device__ __forceinline__ float ex2f(float x) {
    float y; asm("ex2.approx.ftz.f32 %0, %1;" : "=f"(y) : "f"(x)); return y;
}
__device__ __forceinline__ u64 pk2(float lo, float hi) {
    u64 r; asm("mov.b64 %0, {%1, %2};" : "=l"(r) : "f"(lo), "f"(hi)); return r;
}
__device__ __forceinline__ void upk2(u64 v, float& lo, float& hi) {
    asm("mov.b64 {%0, %1}, %2;" : "=f"(lo), "=f"(hi) : "l"(v));
}
__device__ __forceinline__ u64 fma2(u64 a, u64 b, u64 c) {
    u64 d; asm("fma.rn.f32x2 %0, %1, %2, %3;" : "=l"(d) : "l"(a), "l"(b), "l"(c)); return d;
}
__device__ __forceinline__ u64 mul2(u64 a, u64 b) {
    u64 d; asm("mul.rn.f32x2 %0, %1, %2;" : "=l"(d) : "l"(a), "l"(b)); return d;
}
__device__ __forceinline__ u64 add2(u64 a, u64 b) {
    u64 d; asm("add.rn.f32x2 %0, %1, %2;" : "=l"(d) : "l"(a), "l"(b)); return d;
}

// ---------------------------------------------------------------------------
// Fused kernel: per-CTA K/V projection of its key tile + attention partials.
// K/V key-pair packed: u64 = (val[key 2j], val[key 2j+1]) per dim.
// QPT=4 queries/thread for ILP across the ex2 dependency chain.
// Bounded scores (|s_log2| < ~12) -> no max subtraction.
// ---------------------------------------------------------------------------
__global__ void __launch_bounds__(THREADS)
attn_kernel(const float* __restrict__ x,
            const float* __restrict__ theta,
            const float* __restrict__ Wk,
            const float* __restrict__ Wv) {
    __shared__ ulonglong2 Ka[KT/2];      // (d0 pair, d1 pair) per key-pair
    __shared__ ulonglong2 Kb[KT/2];      // (d2 pair, d3 pair)
    __shared__ ulonglong2 Va[KT/2];
    __shared__ ulonglong2 Vb[KT/2];
    __shared__ float wk[DK * EE];
    __shared__ float wv[DK * EE];

    int tid = threadIdx.x;               // 0..127
    int qb  = blockIdx.x;                // 0..3
    int bh  = blockIdx.y;                // 0..15
    int ks  = blockIdx.z;                // 0..15
    int b = bh >> 2, h = bh & 3;

    if (tid < DK * EE) {
        wk[tid] = Wk[h * DK * EE + tid];
        wv[tid] = Wv[h * DK * EE + tid];
    }

    // ---- queries: q = cos(x+theta) * (0.5*log2 e), duplicated-packed ----
    const float4 thv = *reinterpret_cast<const float4*>(theta + h * DK);
    const float SCL = 0.72134752044448170368f;   // 0.5 * log2(e)
    u64 qd0[QPT], qd1[QPT], qd2[QPT], qd3[QPT];
    int sq0 = qb * QBLK + tid;
    #pragma unroll
    for (int qi = 0; qi < QPT; qi++) {
        int sq = sq0 + qi * THREADS;
        const float4 xq = *reinterpret_cast<const float4*>(
            x + (b * SS + sq) * EE + h * DK);
        float c0 = __cosf(xq.x + thv.x) * SCL;
        float c1 = __cosf(xq.y + thv.y) * SCL;
        float c2 = __cosf(xq.z + thv.z) * SCL;
        float c3 = __cosf(xq.w + thv.w) * SCL;
        qd0[qi] = pk2(c0, c0); qd1[qi] = pk2(c1, c1);
        qd2[qi] = pk2(c2, c2); qd3[qi] = pk2(c3, c3);
    }
    __syncthreads();

    // ---- K/V tile build: thread t<64 computes key tokens (2t, 2t+1) ----
    if (tid < KT/2) {
        float kk[2][DK], vv[2][DK];
        #pragma unroll
        for (int t = 0; t < 2; t++) {
            int tok = 2 * tid + t;
            const float4* x4 = reinterpret_cast<const float4*>(
                x + ((b * SS + ks * KT) + tok) * EE);
            float xr[EE];
            #pragma unroll
            for (int r = 0; r < 4; r++) {
                float4 q = x4[r];
                xr[4*r+0] = q.x; xr[4*r+1] = q.y; xr[4*r+2] = q.z; xr[4*r+3] = q.w;
            }
            #pragma unroll
            for (int d = 0; d < DK; d++) {
                float a = 0.f, c = 0.f;
                #pragma unroll
                for (int e = 0; e < EE; e++) {
                    a = fmaf(xr[e], wk[d * EE + e], a);
                    c = fmaf(xr[e], wv[d * EE + e], c);
                }
                kk[t][d] = a; vv[t][d] = c;
            }
        }
        ulonglong2 t0, t1;
        t0.x = pk2(kk[0][0], kk[1][0]); t0.y = pk2(kk[0][1], kk[1][1]);
        t1.x = pk2(kk[0][2], kk[1][2]); t1.y = pk2(kk[0][3], kk[1][3]);
        Ka[tid] = t0; Kb[tid] = t1;
        t0.x = pk2(vv[0][0], vv[1][0]); t0.y = pk2(vv[0][1], vv[1][1]);
        t1.x = pk2(vv[0][2], vv[1][2]); t1.y = pk2(vv[0][3], vv[1][3]);
        Va[tid] = t0; Vb[tid] = t1;
    }
    __syncthreads();

    u64 A0[QPT], A1[QPT], A2[QPT], A3[QPT], L[QPT];
    #pragma unroll
    for (int qi = 0; qi < QPT; qi++) {
        A0[qi] = 0ULL; A1[qi] = 0ULL; A2[qi] = 0ULL; A3[qi] = 0ULL; L[qi] = 0ULL;
    }

    #pragma unroll 4
    for (int jp = 0; jp < KT/2; jp++) {
        ulonglong2 ka = Ka[jp];              // broadcast LDS.128
        ulonglong2 kb = Kb[jp];
        ulonglong2 va = Va[jp];
        ulonglong2 vb = Vb[jp];
        #pragma unroll
        for (int qi = 0; qi < QPT; qi++) {
            u64 s = mul2(qd0[qi], ka.x);
            s = fma2(qd1[qi], ka.y, s);
            s = fma2(qd2[qi], kb.x, s);
            s = fma2(qd3[qi], kb.y, s);       // (score_even, score_odd)
            float se, so; upk2(s, se, so);
            u64 pp = pk2(ex2f(se), ex2f(so));
            L[qi]  = add2(L[qi], pp);
            A0[qi] = fma2(pp, va.x, A0[qi]);
            A1[qi] = fma2(pp, va.y, A1[qi]);
            A2[qi] = fma2(pp, vb.x, A2[qi]);
            A3[qi] = fma2(pp, vb.y, A3[qi]);
        }
    }

    // coalesced partial stores: [ks][h][b][sq] (lane-consecutive sq)
    int rowbase = ((ks * HH + h) * BB + b) * SS;
    #pragma unroll
    for (int qi = 0; qi < QPT; qi++) {
        int sq = sq0 + qi * THREADS;
        int idx = rowbase + sq;
        float e0, o0, e1, o1, e2, o2, e3, o3, le, lo;
        upk2(A0[qi], e0, o0); upk2(A1[qi], e1, o1);
        upk2(A2[qi], e2, o2); upk2(A3[qi], e3, o3);
        upk2(L[qi], le, lo);
        reinterpret_cast<float4*>(g_parta)[idx] =
            make_float4(e0 + o0, e1 + o1, e2 + o2, e3 + o3);
        g_partl[idx] = le + lo;
    }
}

// ---------------------------------------------------------------------------
// Epilogue: CTA = 32 tokens x 4 heads (128 threads, one (token,h) each).
// ks-loop loads are 4-lines/instr (optimal): lane-consecutive sq within each
// h group. Dual accumulator sets (even/odd ks) break the add chain so loads
// pipeline. Then normalize + out = att @ Wc^T (transposed Wc in smem).
// ---------------------------------------------------------------------------
#define EPI_TOK 32
#define SPLANE (BB * SS)     // float4-row stride between h groups

__global__ void __launch_bounds__(128)
epi_kernel(const float* __restrict__ Wc, float* __restrict__ out) {
    __shared__ float wct[EE * EE];            // wct[e*16+o] = Wc[o*16+e]
    __shared__ float att[EPI_TOK][EE + 1];

    int tid = threadIdx.x;                    // 0..127
    {   // transposed Wc load (two elements per thread)
        int i0 = tid, i1 = tid + 128;
        wct[(i0 & 15) * EE + (i0 >> 4)] = Wc[i0];
        wct[(i1 & 15) * EE + (i1 >> 4)] = Wc[i1];
    }

    int tl = tid >> 2;                        // local token 0..31
    int h  = tid & 3;
    int tok = blockIdx.x * EPI_TOK + tl;      // global token
    int b  = tok >> 11;
    int sq = tok & (SS - 1);

    const float4* pa = reinterpret_cast<const float4*>(g_parta);
    const float*  pl = g_partl;
    int base = (h * BB + b) * SS + sq;        // ks=0 row

    // dual accumulator sets over even/odd ks -> independent load chains
    float4 Ae = make_float4(0.f,0.f,0.f,0.f), Ao = make_float4(0.f,0.f,0.f,0.f);
    float le = 0.f, lo = 0.f;
    #pragma unroll
    for (int ks = 0; ks < KSPLIT; ks += 2) {
        int i0 = base + (ks    ) * (HH * SPLANE);
        int i1 = base + (ks + 1) * (HH * SPLANE);
        float4 t0 = pa[i0];
        float4 t1 = pa[i1];
        float  u0 = pl[i0];
        float  u1 = pl[i1];
        Ae.x += t0.x; Ae.y += t0.y; Ae.z += t0.z; Ae.w += t0.w; le += u0;
        Ao.x += t1.x; Ao.y += t1.y; Ao.z += t1.z; Ao.w += t1.w; lo += u1;
    }
    float ax = Ae.x + Ao.x, ay = Ae.y + Ao.y;
    float az = Ae.z + Ao.z, aw = Ae.w + Ao.w;
    float inv = 1.0f / (le + lo);

    float* arow = att[tl] + h * DK;
    arow[0] = ax * inv; arow[1] = ay * inv;
    arow[2] = az * inv; arow[3] = aw * inv;
    __syncthreads();

    const float* ar = att[tl];
    float r[4] = {0.f, 0.f, 0.f, 0.f};
    #pragma unroll
    for (int e = 0; e < EE; e++) {
        float av = ar[e];
        #pragma unroll
        for (int d = 0; d < 4; d++)
            r[d] = fmaf(av, wct[e * EE + h * 4 + d], r[d]);
    }
    reinterpret_cast<float4*>(out + tok * EE)[h] =
        make_float4(r[0], r[1], r[2], r[3]);
}

// ---------------------------------------------------------------------------
extern "C" void kernel_launch(void* const* d_in, const int* in_sizes, int n_in,
                              void* d_out, int out_size) {
    const float* x     = (const float*)d_in[0];
    const float* theta = (const float*)d_in[1];
    const float* Wk    = (const float*)d_in[2];
    const float* Wv    = (const float*)d_in[3];
    const float* Wc    = (const float*)d_in[4];
    float* out = (float*)d_out;

    attn_kernel<<<dim3(SS / QBLK, NBH, KSPLIT), THREADS>>>(x, theta, Wk, Wv);
    epi_kernel<<<(BB * SS) / EPI_TOK, 128>>>(Wc, out);
}

// round 13
// speedup vs baseline: 1.1701x; 1.0491x over previous
#include <cuda_runtime.h>

// Problem constants (fixed by the reference): B=4, S=2048, E=16, H=4, D_K=4
#define BB 4
#define SS 2048
#define EE 16
#define HH 4
#define DK 4
#define NBH (BB*HH)

#define KSPLIT 16
#define KT (SS/KSPLIT)       // 128 keys per split tile
#define THREADS 128
#define QPT 4
#define QBLK (THREADS*QPT)   // 512 queries per CTA

typedef unsigned long long u64;

// Scratch (allocation-free rule: __device__ globals)
// Layout: parta[ks][h][b][sq] as float4 rows; partl[ks][h][b][sq] scalar.
// attn stores lane-consecutive sq (coalesced); epi reads 4-lines/instr.
__device__ float g_parta[KSPLIT * BB * SS * EE];
__device__ float g_partl[KSPLIT * BB * SS * HH];

__device__ __forceinline__ float ex2f(float x) {
    float y; asm("ex2.approx.ftz.f32 %0, %1;" : "=f"(y) : "f"(x)); return y;
}
__device__ __forceinline__ u64 pk2(float lo, float hi) {
    u64 r; asm("mov.b64 %0, {%1, %2};" : "=l"(r) : "f"(lo), "f"(hi)); return r;
}
__device__ __forceinline__ void upk2(u64 v, float& lo, float& hi) {
    asm("mov.b64 {%0, %1}, %2;" : "=f"(lo), "=f"(hi) : "l"(v));
}
__device__ __forceinline__ u64 fma2(u64 a, u64 b, u64 c) {
    u64 d; asm("fma.rn.f32x2 %0, %1, %2, %3;" : "=l"(d) : "l"(a), "l"(b), "l"(c)); return d;
}
__device__ __forceinline__ u64 mul2(u64 a, u64 b) {
    u64 d; asm("mul.rn.f32x2 %0, %1, %2;" : "=l"(d) : "l"(a), "l"(b)); return d;
}
__device__ __forceinline__ u64 add2(u64 a, u64 b) {
    u64 d; asm("add.rn.f32x2 %0, %1, %2;" : "=l"(d) : "l"(a), "l"(b)); return d;
}

// ---------------------------------------------------------------------------
// Fused kernel (FROZEN from round 12): per-CTA K/V projection + attention
// partials. K/V key-pair packed; QPT=4 for ILP; bounded scores -> no max.
// ---------------------------------------------------------------------------
__global__ void __launch_bounds__(THREADS)
attn_kernel(const float* __restrict__ x,
            const float* __restrict__ theta,
            const float* __restrict__ Wk,
            const float* __restrict__ Wv) {
    __shared__ ulonglong2 Ka[KT/2];      // (d0 pair, d1 pair) per key-pair
    __shared__ ulonglong2 Kb[KT/2];      // (d2 pair, d3 pair)
    __shared__ ulonglong2 Va[KT/2];
    __shared__ ulonglong2 Vb[KT/2];
    __shared__ float wk[DK * EE];
    __shared__ float wv[DK * EE];

    int tid = threadIdx.x;               // 0..127
    int qb  = blockIdx.x;                // 0..3
    int bh  = blockIdx.y;                // 0..15
    int ks  = blockIdx.z;                // 0..15
    int b = bh >> 2, h = bh & 3;

    if (tid < DK * EE) {
        wk[tid] = Wk[h * DK * EE + tid];
        wv[tid] = Wv[h * DK * EE + tid];
    }

    // ---- queries: q = cos(x+theta) * (0.5*log2 e), duplicated-packed ----
    const float4 thv = *reinterpret_cast<const float4*>(theta + h * DK);
    const float SCL = 0.72134752044448170368f;   // 0.5 * log2(e)
    u64 qd0[QPT], qd1[QPT], qd2[QPT], qd3[QPT];
    int sq0 = qb * QBLK + tid;
    #pragma unroll
    for (int qi = 0; qi < QPT; qi++) {
        int sq = sq0 + qi * THREADS;
        const float4 xq = *reinterpret_cast<const float4*>(
            x + (b * SS + sq) * EE + h * DK);
        float c0 = __cosf(xq.x + thv.x) * SCL;
        float c1 = __cosf(xq.y + thv.y) * SCL;
        float c2 = __cosf(xq.z + thv.z) * SCL;
        float c3 = __cosf(xq.w + thv.w) * SCL;
        qd0[qi] = pk2(c0, c0); qd1[qi] = pk2(c1, c1);
        qd2[qi] = pk2(c2, c2); qd3[qi] = pk2(c3, c3);
    }
    __syncthreads();

    // ---- K/V tile build: thread t<64 computes key tokens (2t, 2t+1) ----
    if (tid < KT/2) {
        float kk[2][DK], vv[2][DK];
        #pragma unroll
        for (int t = 0; t < 2; t++) {
            int tok = 2 * tid + t;
            const float4* x4 = reinterpret_cast<const float4*>(
                x + ((b * SS + ks * KT) + tok) * EE);
            float xr[EE];
            #pragma unroll
            for (int r = 0; r < 4; r++) {
                float4 q = x4[r];
                xr[4*r+0] = q.x; xr[4*r+1] = q.y; xr[4*r+2] = q.z; xr[4*r+3] = q.w;
            }
            #pragma unroll
            for (int d = 0; d < DK; d++) {
                float a = 0.f, c = 0.f;
                #pragma unroll
                for (int e = 0; e < EE; e++) {
                    a = fmaf(xr[e], wk[d * EE + e], a);
                    c = fmaf(xr[e], wv[d * EE + e], c);
                }
                kk[t][d] = a; vv[t][d] = c;
            }
        }
        ulonglong2 t0, t1;
        t0.x = pk2(kk[0][0], kk[1][0]); t0.y = pk2(kk[0][1], kk[1][1]);
        t1.x = pk2(kk[0][2], kk[1][2]); t1.y = pk2(kk[0][3], kk[1][3]);
        Ka[tid] = t0; Kb[tid] = t1;
        t0.x = pk2(vv[0][0], vv[1][0]); t0.y = pk2(vv[0][1], vv[1][1]);
        t1.x = pk2(vv[0][2], vv[1][2]); t1.y = pk2(vv[0][3], vv[1][3]);
        Va[tid] = t0; Vb[tid] = t1;
    }
    __syncthreads();

    u64 A0[QPT], A1[QPT], A2[QPT], A3[QPT], L[QPT];
    #pragma unroll
    for (int qi = 0; qi < QPT; qi++) {
        A0[qi] = 0ULL; A1[qi] = 0ULL; A2[qi] = 0ULL; A3[qi] = 0ULL; L[qi] = 0ULL;
    }

    #pragma unroll 4
    for (int jp = 0; jp < KT/2; jp++) {
        ulonglong2 ka = Ka[jp];              // broadcast LDS.128
        ulonglong2 kb = Kb[jp];
        ulonglong2 va = Va[jp];
        ulonglong2 vb = Vb[jp];
        #pragma unroll
        for (int qi = 0; qi < QPT; qi++) {
            u64 s = mul2(qd0[qi], ka.x);
            s = fma2(qd1[qi], ka.y, s);
            s = fma2(qd2[qi], kb.x, s);
            s = fma2(qd3[qi], kb.y, s);       // (score_even, score_odd)
            float se, so; upk2(s, se, so);
            u64 pp = pk2(ex2f(se), ex2f(so));
            L[qi]  = add2(L[qi], pp);
            A0[qi] = fma2(pp, va.x, A0[qi]);
            A1[qi] = fma2(pp, va.y, A1[qi]);
            A2[qi] = fma2(pp, vb.x, A2[qi]);
            A3[qi] = fma2(pp, vb.y, A3[qi]);
        }
    }

    // coalesced partial stores: [ks][h][b][sq] (lane-consecutive sq)
    int rowbase = ((ks * HH + h) * BB + b) * SS;
    #pragma unroll
    for (int qi = 0; qi < QPT; qi++) {
        int sq = sq0 + qi * THREADS;
        int idx = rowbase + sq;
        float e0, o0, e1, o1, e2, o2, e3, o3, le, lo;
        upk2(A0[qi], e0, o0); upk2(A1[qi], e1, o1);
        upk2(A2[qi], e2, o2); upk2(A3[qi], e3, o3);
        upk2(L[qi], le, lo);
        reinterpret_cast<float4*>(g_parta)[idx] =
            make_float4(e0 + o0, e1 + o1, e2 + o2, e3 + o3);
        g_partl[idx] = le + lo;
    }
}

// ---------------------------------------------------------------------------
// Epilogue: CTA = 16 tokens, 256 threads. Thread = (sg = tid>>6, token-head
// = tid&63). Each thread reads 4 ks-planes (4 float4 + 4 scalar, all
// independent; each warp-LDG touches exactly 4 lines since (tl,h) are the
// low lane bits). Split-groups combine in smem, then 64 threads normalize
// and do out = att @ Wc^T (transposed Wc in smem).
// ---------------------------------------------------------------------------
#define EPI_TOK 16
#define EPI_THREADS 256
#define SPLANE (BB * SS)     // float4-row stride between h groups

__global__ void __launch_bounds__(EPI_THREADS)
epi_kernel(const float* __restrict__ Wc, float* __restrict__ out) {
    __shared__ float wct[EE * EE];            // wct[e*16+o] = Wc[o*16+e]
    __shared__ float ps[4 * 64 * 5];          // [sg][token-head][5], stride-5
    __shared__ float att[EPI_TOK][EE + 1];

    int tid = threadIdx.x;                    // 0..255
    wct[(tid & 15) * EE + (tid >> 4)] = Wc[tid];

    int sg    = tid >> 6;                     // split-group 0..3 (4 ks each)
    int local = tid & 63;                     // token-head
    int tl = local >> 2;                      // local token 0..15
    int h  = local & 3;
    int tok = blockIdx.x * EPI_TOK + tl;
    int b  = tok >> 11;
    int sq = tok & (SS - 1);

    const float4* pa = reinterpret_cast<const float4*>(g_parta);
    const float*  pl = g_partl;
    int base = (h * BB + b) * SS + sq;        // ks=0 row
    int i0 = base + (sg * 4 + 0) * (HH * SPLANE);
    int i1 = base + (sg * 4 + 1) * (HH * SPLANE);
    int i2 = base + (sg * 4 + 2) * (HH * SPLANE);
    int i3 = base + (sg * 4 + 3) * (HH * SPLANE);

    float4 t0 = pa[i0], t1 = pa[i1], t2 = pa[i2], t3 = pa[i3];
    float  u0 = pl[i0], u1 = pl[i1], u2 = pl[i2], u3 = pl[i3];

    float ax = (t0.x + t1.x) + (t2.x + t3.x);
    float ay = (t0.y + t1.y) + (t2.y + t3.y);
    float az = (t0.z + t1.z) + (t2.z + t3.z);
    float aw = (t0.w + t1.w) + (t2.w + t3.w);
    float l  = (u0 + u1) + (u2 + u3);

    float* row = ps + tid * 5;                // stride 5: conflict-free
    row[0] = ax; row[1] = ay; row[2] = az; row[3] = aw; row[4] = l;
    __syncthreads();

    if (tid < 64) {
        const float* p0 = ps + tid * 5;
        const float* p1 = p0 + 64 * 5;
        const float* p2 = p1 + 64 * 5;
        const float* p3 = p2 + 64 * 5;
        float a0 = (p0[0] + p1[0]) + (p2[0] + p3[0]);
        float a1 = (p0[1] + p1[1]) + (p2[1] + p3[1]);
        float a2 = (p0[2] + p1[2]) + (p2[2] + p3[2]);
        float a3 = (p0[3] + p1[3]) + (p2[3] + p3[3]);
        float ll = (p0[4] + p1[4]) + (p2[4] + p3[4]);
        float inv = 1.0f / ll;
        float* arow = att[tl] + h * DK;
        arow[0] = a0 * inv; arow[1] = a1 * inv;
        arow[2] = a2 * inv; arow[3] = a3 * inv;
    }
    __syncthreads();

    if (tid < 64) {
        const float* ar = att[tl];
        float r[4] = {0.f, 0.f, 0.f, 0.f};
        #pragma unroll
        for (int e = 0; e < EE; e++) {
            float av = ar[e];
            #pragma unroll
            for (int d = 0; d < 4; d++)
                r[d] = fmaf(av, wct[e * EE + h * 4 + d], r[d]);
        }
        reinterpret_cast<float4*>(out + tok * EE)[h] =
            make_float4(r[0], r[1], r[2], r[3]);
    }
}

// ---------------------------------------------------------------------------
extern "C" void kernel_launch(void* const* d_in, const int* in_sizes, int n_in,
                              void* d_out, int out_size) {
    const float* x     = (const float*)d_in[0];
    const float* theta = (const float*)d_in[1];
    const float* Wk    = (const float*)d_in[2];
    const float* Wv    = (const float*)d_in[3];
    const float* Wc    = (const float*)d_in[4];
    float* out = (float*)d_out;

    attn_kernel<<<dim3(SS / QBLK, NBH, KSPLIT), THREADS>>>(x, theta, Wk, Wv);
    epi_kernel<<<(BB * SS) / EPI_TOK, EPI_THREADS>>>(Wc, out);
}